// round 15
// baseline (speedup 1.0000x reference)
#include <cuda_runtime.h>
#include <cstdint>

// ImprovedVectorizationLoss: fused masked-L1 + BCE + continuity + recon-MSE.
// R15: warp-autonomous streaming. Each warp owns 32-record chunks with a
// private double-buffered cp.async pipeline (per-thread commit/wait groups),
// ballot+shfl continuity, NO __syncthreads in the hot loop. Chunk-boundary
// continuity via per-chunk first/last tables + last-block fixup.

#define M_ROW 4096
#define TPB   256
#define WPB   8
#define CHUNK 32
#define CPR   (M_ROW / CHUNK)        // 128 chunks per row
#define NBLOCKS 740                  // 5 blocks/SM x 148 SMs
#define NWARP (NBLOCKS * WPB)        // 5920
#define BMAX  512
#define EPSV  1e-7f

__device__ float        g_acc[6];    // [coord,width,bce,nvalid,cont,recon]
__device__ unsigned int g_ticket;
__device__ int          g_first_flag[BMAX * CPR];
__device__ float2       g_first_p45[BMAX * CPR];
__device__ float2       g_last_p45[BMAX * CPR];

__device__ __forceinline__ float warpReduceSumF(float v) {
#pragma unroll
    for (int o = 16; o > 0; o >>= 1) v += __shfl_down_sync(0xffffffffu, v, o);
    return v;
}

__device__ __forceinline__ void cp16(void* s, const void* g) {
    unsigned saddr = (unsigned)__cvta_generic_to_shared(s);
    asm volatile("cp.async.cg.shared.global [%0], [%1], 16;" :: "r"(saddr), "l"(g));
}
#define CP_COMMIT() asm volatile("cp.async.commit_group;")
#define CP_WAIT(n)  asm volatile("cp.async.wait_group %0;" :: "n"(n))

// Stage one 32-record chunk (preds 288 floats + tgts 288 floats) into dst.
// Warp-scope; 72 float4 per tensor; uniform commit count per thread.
__device__ __forceinline__ void stage_chunk(
    const float* __restrict__ preds, const float* __restrict__ tgts,
    int c, float* dst, int lane)
{
    const float4* ps = reinterpret_cast<const float4*>(preds + (size_t)c * (CHUNK * 9));
    const float4* ts = reinterpret_cast<const float4*>(tgts  + (size_t)c * (CHUNK * 9));
    float4* d4 = reinterpret_cast<float4*>(dst);
#pragma unroll
    for (int r = 0; r < 2; r++) {
        int i = lane + r * 32;
        cp16(&d4[i],      &ps[i]);
        cp16(&d4[72 + i], &ts[i]);
    }
    if (lane < 8) {
        int i = lane + 64;
        cp16(&d4[i],      &ps[i]);
        cp16(&d4[72 + i], &ts[i]);
    }
}

__global__ __launch_bounds__(TPB, 5) void loss_fused_kernel(
    const float* __restrict__ preds, const float* __restrict__ tgts,
    const float* __restrict__ rec,   const float* __restrict__ img,
    float* __restrict__ out, int B, int nrec)
{
    // per-warp double buffers: [warp][buf][preds 288 | tgts 288]
    __shared__ __align__(16) float sbuf[WPB][2][CHUNK * 9 * 2];   // 36864 B
    __shared__ float swred[6][8];
    __shared__ int   slast;

    const int tid  = threadIdx.x;
    const int bid  = blockIdx.x;
    const int lane = tid & 31;
    const int wid  = tid >> 5;
    const int gw   = bid * WPB + wid;       // global warp id
    const int NCHUNK = B * CPR;

    float coordS = 0.f, widthS = 0.f, bceS = 0.f, nvS = 0.f, contS = 0.f, reconS = 0.f;

    // ---- prologue: prefetch this warp's first two chunks ----
    {
        int c0 = gw;
        if (c0 < NCHUNK) stage_chunk(preds, tgts, c0, &sbuf[wid][0][0], lane);
        CP_COMMIT();
        int c1 = gw + NWARP;
        if (c1 < NCHUNK) stage_chunk(preds, tgts, c1, &sbuf[wid][1][0], lane);
        CP_COMMIT();
    }

    // ---- recon MSE (grid-stride) overlaps the first fills ----
    {
        const float4* r4 = reinterpret_cast<const float4*>(rec);
        const float4* i4 = reinterpret_cast<const float4*>(img);
        const int n4 = nrec >> 2;
        for (int i = bid * TPB + tid; i < n4; i += NBLOCKS * TPB) {
            float4 r = r4[i], m = i4[i];
            float dx = r.x - m.x, dy = r.y - m.y, dz = r.z - m.z, dw = r.w - m.w;
            reconS += dx * dx + dy * dy + dz * dz + dw * dw;
        }
    }

    // ---- warp-private chunk pipeline (no __syncthreads) ----
    int k = 0;
    for (int c = gw; c < NCHUNK; c += NWARP, k++) {
        const int d = k & 1;
        CP_WAIT(1);            // per-thread: buffer d's group complete
        __syncwarp();

        const float* pr = &sbuf[wid][d][lane * 9];
        const float* tr = &sbuf[wid][d][CHUNK * 9 + lane * 9];

        float t8   = tr[8];
        bool  v    = (t8 > 0.5f);
        float mask = v ? 1.0f : 0.0f;
        float a4 = pr[4], a5 = pr[5];

        coordS += (fabsf(pr[0] - tr[0]) + fabsf(pr[1] - tr[1]) + fabsf(pr[2] - tr[2])
                 + fabsf(pr[3] - tr[3]) + fabsf(a4 - tr[4]) + fabsf(a5 - tr[5])) * mask;
        widthS += (fabsf(pr[6] - tr[6]) + fabsf(pr[7] - tr[7])) * mask;
        float p = fminf(fmaxf(pr[8], EPSV), 1.0f - EPSV);
        bceS   += -(t8 * __logf(p) + (1.0f - t8) * __logf(1.0f - p));
        nvS    += mask;

        // continuity inside the chunk: ballot + shfl
        unsigned b   = __ballot_sync(0xffffffffu, v);
        unsigned rem = (lane < 31) ? (b & (0xFFFFFFFEu << lane)) : 0u;
        int nx = rem ? (__ffs(rem) - 1) : 0;
        float nbx = __shfl_sync(0xffffffffu, a4, nx);
        float nby = __shfl_sync(0xffffffffu, a5, nx);
        if (v) {
            if (rem) {
                contS += 0.5f * (fabsf(a4 - nbx) + fabsf(a5 - nby));
            } else {
                g_last_p45[c] = make_float2(a4, a5);   // chunk's last valid
            }
        }
        int f = __ffs(b) - 1;                          // -1 if b==0
        if (lane == 0) g_first_flag[c] = (b != 0u) ? 1 : 0;
        if (b != 0u && lane == f) g_first_p45[c] = make_float2(a4, a5);

        __syncwarp();          // all lanes done reading buffer d

        // refill buffer d with the chunk two steps ahead
        int cn = c + 2 * NWARP;
        if (cn < NCHUNK) stage_chunk(preds, tgts, cn, &sbuf[wid][d][0], lane);
        CP_COMMIT();
    }
    CP_WAIT(0);                // drain before smem reuse / exit

    // ---- block reduce + global atomic accumulate ----
    float vals[6] = {coordS, widthS, bceS, nvS, contS, reconS};
#pragma unroll
    for (int q = 0; q < 6; q++) {
        float v = warpReduceSumF(vals[q]);
        if (lane == 0) swred[q][wid] = v;
    }
    __syncthreads();
    if (wid == 0 && lane < 6) {
        float v = 0.f;
#pragma unroll
        for (int j = 0; j < 8; j++) v += swred[lane][j];
        atomicAdd(&g_acc[lane], v);
    }
    __syncthreads();

    // ---- last-block finalize (single-level ticket) ----
    if (tid == 0) {
        __threadfence();       // release (cumulative)
        unsigned int t = atomicAdd(&g_ticket, 1u);
        slast = (t == (unsigned int)(NBLOCKS - 1)) ? 1 : 0;
    }
    __syncthreads();
    if (!slast) return;
    __threadfence();           // acquire (single block)

    // ---- cross-chunk continuity fixup: one row per thread, batched ----
    float fix = 0.f;
    for (int r = tid; r < B; r += TPB) {
        float2 nf = make_float2(0.f, 0.f);
        bool have = false;
        for (int sb = CPR - 8; sb >= 0; sb -= 8) {
            int    flg[8];
            float2 fp[8], lp[8];
#pragma unroll
            for (int j = 0; j < 8; j++) {
                int c = r * CPR + sb + j;
                flg[j] = g_first_flag[c];
                fp[j]  = g_first_p45[c];
                lp[j]  = g_last_p45[c];
            }
#pragma unroll
            for (int j = 7; j >= 0; j--) {
                if (flg[j]) {
                    if (have) fix += 0.5f * (fabsf(lp[j].x - nf.x) + fabsf(lp[j].y - nf.y));
                    nf = fp[j];
                    have = true;
                }
            }
        }
    }
    {
        float v = warpReduceSumF(fix);
        if (lane == 0) swred[0][wid] = v;
    }
    __syncthreads();
    if (tid == 0) {
        float fsum = 0.f;
#pragma unroll
        for (int j = 0; j < 8; j++) fsum += swred[0][j];

        double t0 = (double)g_acc[0], t1 = (double)g_acc[1], t2 = (double)g_acc[2];
        double nv = (double)g_acc[3];
        double t4 = (double)g_acc[4] + (double)fsum;
        double t5 = (double)g_acc[5];

        double coord    = (nv > 0.0) ? t0 / fmax(nv * 6.0, 1.0) : 0.0;
        double width    = (nv > 0.0) ? t1 / fmax(nv * 2.0, 1.0) : 0.0;
        double validity = t2 / ((double)B * (double)M_ROW);
        double cont     = t4 / (double)B;
        double recon    = t5 / (double)nrec;
        out[0] = (float)(coord + width + 2.0 * validity + 0.2 * cont + 0.1 * recon);

        // self-reset for the next graph replay
        g_ticket = 0u;
#pragma unroll
        for (int q = 0; q < 6; q++) g_acc[q] = 0.f;
        __threadfence();
    }
}

extern "C" void kernel_launch(void* const* d_in, const int* in_sizes, int n_in,
                              void* d_out, int out_size)
{
    const float* preds = (const float*)d_in[0];
    const float* tgts  = (const float*)d_in[1];
    const float* rec   = (const float*)d_in[2];
    const float* img   = (const float*)d_in[3];

    const int B    = in_sizes[0] / (M_ROW * 9);
    const int nrec = in_sizes[2];

    loss_fused_kernel<<<NBLOCKS, TPB>>>(preds, tgts, rec, img,
                                        (float*)d_out, B, nrec);
}

// round 16
// speedup vs baseline: 3.1647x; 3.1647x over previous
#include <cuda_runtime.h>
#include <cstdint>

// ImprovedVectorizationLoss: fused masked-L1 + BCE + continuity + recon-MSE.
// R16: R10's persistent work-stealing cp.async pipeline at 6 blocks/SM
// (888 blocks): s45f removed; continuity = per-32-group ballot+shfl with a
// 16-entry group table (first-valid p45 + flag) resolved post-barrier.

#define M_ROW 4096
#define TPB   256
#define SEGS  8
#define SEG   (M_ROW / SEGS)         // 512
#define TILE  256
#define NTILE (SEG / TILE)           // 2
#define NF4T  (TILE * 9 / 4)         // 576 float4 per tile per tensor
#define NBLOCKS 888                  // 6 blocks/SM x 148 SMs, single wave
#define BMAX  512
#define EPSV  1e-7f

__device__ float        g_acc[6];    // [coord,width,bce,nvalid,cont,recon]
__device__ unsigned int g_ticket;
__device__ unsigned int g_work;
__device__ int          g_first_idx[BMAX * SEGS];   // 0 if any valid, SEG if none
__device__ float2       g_first_p45[BMAX * SEGS];
__device__ float2       g_last_p45[BMAX * SEGS];

__device__ __forceinline__ float warpReduceSumF(float v) {
#pragma unroll
    for (int o = 16; o > 0; o >>= 1) v += __shfl_down_sync(0xffffffffu, v, o);
    return v;
}

__device__ __forceinline__ void cp16(void* s, const void* g) {
    unsigned saddr = (unsigned)__cvta_generic_to_shared(s);
    asm volatile("cp.async.cg.shared.global [%0], [%1], 16;" :: "r"(saddr), "l"(g));
}
#define CP_COMMIT() asm volatile("cp.async.commit_group;")
#define CP_WAIT(n)  asm volatile("cp.async.wait_group %0;" :: "n"(n))

__global__ __launch_bounds__(TPB, 6) void loss_fused_kernel(
    const float* __restrict__ preds, const float* __restrict__ tgts,
    const float* __restrict__ rec,   const float* __restrict__ img,
    float* __restrict__ out, int B, int nrec)
{
    __shared__ float         sp[NTILE * TILE * 9];   // 18 KB
    __shared__ float         st[NTILE * TILE * 9];   // 18 KB
    __shared__ float2        sgrp_first[16];         // per-group first-valid p45
    __shared__ unsigned char sflag[16];              // per-group any-valid flag
    __shared__ float         swred[6][8];
    __shared__ int           s_seg;
    __shared__ int           slast;

    const int tid  = threadIdx.x;
    const int bid  = blockIdx.x;
    const int lane = tid & 31;
    const int wid  = tid >> 5;
    const int NSEG = B * SEGS;

    float coordS = 0.f, widthS = 0.f, bceS = 0.f, nvS = 0.f, contS = 0.f, reconS = 0.f;

    // ---- prologue: steal first segment, prefetch both tiles ----
    if (tid == 0) s_seg = (int)atomicAdd(&g_work, 1u);
    __syncthreads();
    int seg = s_seg;

    if (seg < NSEG) {
        const float4* p4 = reinterpret_cast<const float4*>(preds + (size_t)seg * SEG * 9);
        const float4* t4 = reinterpret_cast<const float4*>(tgts  + (size_t)seg * SEG * 9);
#pragma unroll
        for (int tl = 0; tl < NTILE; tl++) {
            float4* spd = reinterpret_cast<float4*>(sp) + tl * NF4T;
            float4* std_ = reinterpret_cast<float4*>(st) + tl * NF4T;
            for (int i = tid; i < NF4T; i += TPB) {
                cp16(&spd[i], &p4[tl * NF4T + i]);
                cp16(&std_[i], &t4[tl * NF4T + i]);
            }
            CP_COMMIT();
        }
    }

    // ---- recon MSE burst overlaps the first prefetch ----
    {
        const float4* r4 = reinterpret_cast<const float4*>(rec);
        const float4* i4 = reinterpret_cast<const float4*>(img);
        const int n4 = nrec >> 2;
        for (int i = bid * TPB + tid; i < n4; i += NBLOCKS * TPB) {
            float4 r = r4[i], m = i4[i];
            float dx = r.x - m.x, dy = r.y - m.y, dz = r.z - m.z, dw = r.w - m.w;
            reconS += dx * dx + dy * dy + dz * dz + dw * dw;
        }
    }

    // ---- persistent segment loop ----
    while (seg < NSEG) {
        if (tid == 0) s_seg = (int)atomicAdd(&g_work, 1u);   // steal next early

        unsigned pend0 = 0u, pend1 = 0u;   // "last valid in my group" markers
        float2   q45[2];
#pragma unroll
        for (int tile = 0; tile < NTILE; tile++) {
            if (tile == 0) CP_WAIT(1); else CP_WAIT(0);
            __syncthreads();   // tile data visible (also publishes s_seg)

            const float* pr = sp + (tile * TILE + tid) * 9;
            const float* tr = st + (tile * TILE + tid) * 9;
            float t8   = tr[8];
            bool  v    = (t8 > 0.5f);
            float mask = v ? 1.0f : 0.0f;

            float a4 = pr[4], a5 = pr[5];
            coordS += (fabsf(pr[0] - tr[0]) + fabsf(pr[1] - tr[1]) + fabsf(pr[2] - tr[2])
                     + fabsf(pr[3] - tr[3]) + fabsf(a4 - tr[4]) + fabsf(a5 - tr[5])) * mask;
            widthS += (fabsf(pr[6] - tr[6]) + fabsf(pr[7] - tr[7])) * mask;

            float p = fminf(fmaxf(pr[8], EPSV), 1.0f - EPSV);
            bceS   += -(t8 * __logf(p) + (1.0f - t8) * __logf(1.0f - p));
            nvS    += mask;

            q45[tile] = make_float2(a4, a5);

            // in-warp continuity: ballot + shfl (no smem array)
            unsigned b   = __ballot_sync(0xffffffffu, v);
            unsigned rem = (lane < 31) ? (b & (0xFFFFFFFEu << lane)) : 0u;
            int nx = rem ? (__ffs(rem) - 1) : 0;
            float nbx = __shfl_sync(0xffffffffu, a4, nx);
            float nby = __shfl_sync(0xffffffffu, a5, nx);
            if (v && rem) contS += 0.5f * (fabsf(a4 - nbx) + fabsf(a5 - nby));
            if (tile == 0) pend0 = (v && !rem) ? 1u : 0u;
            else           pend1 = (v && !rem) ? 1u : 0u;

            const int g = tile * 8 + wid;
            if (b != 0u && lane == (__ffs(b) - 1)) sgrp_first[g] = make_float2(a4, a5);
            if (lane == 0) sflag[g] = (b != 0u) ? 1 : 0;
        }
        __syncthreads();   // sp/st consumed; group tables visible

        const int segn = s_seg;

        // ---- prefetch next segment into the freed buffers ----
        if (segn < NSEG) {
            const float4* p4 = reinterpret_cast<const float4*>(preds + (size_t)segn * SEG * 9);
            const float4* t4 = reinterpret_cast<const float4*>(tgts  + (size_t)segn * SEG * 9);
#pragma unroll
            for (int tl = 0; tl < NTILE; tl++) {
                float4* spd = reinterpret_cast<float4*>(sp) + tl * NF4T;
                float4* std_ = reinterpret_cast<float4*>(st) + tl * NF4T;
                for (int i = tid; i < NF4T; i += TPB) {
                    cp16(&spd[i], &p4[tl * NF4T + i]);
                    cp16(&std_[i], &t4[tl * NF4T + i]);
                }
                CP_COMMIT();
            }
        }

        // ---- cross-group continuity resolution (under the prefetch) ----
        const int rs = seg;
#pragma unroll
        for (int t = 0; t < 2; t++) {
            unsigned pend = t ? pend1 : pend0;
            if (pend) {
                const int g = t * 8 + wid;
                bool found = false;
                float2 nb = make_float2(0.f, 0.f);
                for (int g2 = g + 1; g2 < 16 && !found; g2++) {
                    if (sflag[g2]) { nb = sgrp_first[g2]; found = true; }
                }
                if (found) {
                    contS += 0.5f * (fabsf(q45[t].x - nb.x) + fabsf(q45[t].y - nb.y));
                } else {
                    g_last_p45[rs] = q45[t];   // unique last valid in segment
                }
            }
        }
        if (tid == 0) {
            int fg = -1;
#pragma unroll
            for (int g2 = 15; g2 >= 0; g2--)
                if (sflag[g2]) fg = g2;
            g_first_idx[rs] = (fg >= 0) ? 0 : SEG;
            if (fg >= 0) g_first_p45[rs] = sgrp_first[fg];
        }

        seg = segn;
        // loop-top CP_WAIT+syncthreads orders these table reads before the
        // next segment's table writes.
    }

    // ---- block reduce + global atomic accumulate ----
    float vals[6] = {coordS, widthS, bceS, nvS, contS, reconS};
#pragma unroll
    for (int q = 0; q < 6; q++) {
        float v = warpReduceSumF(vals[q]);
        if (lane == 0) swred[q][wid] = v;
    }
    __syncthreads();
    if (wid == 0 && lane < 6) {
        float v = 0.f;
#pragma unroll
        for (int j = 0; j < 8; j++) v += swred[lane][j];
        atomicAdd(&g_acc[lane], v);
    }
    __syncthreads();

    // ---- last-block finalize ----
    if (tid == 0) {
        __threadfence();   // release: publishes this block's writes (cumulative)
        unsigned int t = atomicAdd(&g_ticket, 1u);
        slast = (t == (unsigned int)(NBLOCKS - 1)) ? 1 : 0;
    }
    __syncthreads();
    if (!slast) return;
    __threadfence();       // acquire (single block)

    // cross-segment continuity fixup: one row per thread, prefetched loads
    float fix = 0.f;
    for (int r = tid; r < B; r += TPB) {
        int    fidx[SEGS];
        float2 fp[SEGS], lp[SEGS];
#pragma unroll
        for (int s = 0; s < SEGS; s++) {
            int q = r * SEGS + s;
            fidx[s] = g_first_idx[q];
            fp[s]   = g_first_p45[q];
            lp[s]   = g_last_p45[q];
        }
        float2 nf = make_float2(0.f, 0.f);
        bool have = false;
#pragma unroll
        for (int s = SEGS - 1; s >= 0; s--) {
            if (fidx[s] < SEG) {
                if (have) fix += 0.5f * (fabsf(lp[s].x - nf.x) + fabsf(lp[s].y - nf.y));
                nf = fp[s];
                have = true;
            }
        }
    }
    {
        float v = warpReduceSumF(fix);
        if (lane == 0) swred[0][wid] = v;
    }
    __syncthreads();
    if (tid == 0) {
        float fsum = 0.f;
#pragma unroll
        for (int j = 0; j < 8; j++) fsum += swred[0][j];

        double t0 = (double)g_acc[0], t1 = (double)g_acc[1], t2 = (double)g_acc[2];
        double nv = (double)g_acc[3];
        double t4 = (double)g_acc[4] + (double)fsum;
        double t5 = (double)g_acc[5];

        double coord    = (nv > 0.0) ? t0 / fmax(nv * 6.0, 1.0) : 0.0;
        double width    = (nv > 0.0) ? t1 / fmax(nv * 2.0, 1.0) : 0.0;
        double validity = t2 / ((double)B * (double)M_ROW);
        double cont     = t4 / (double)B;
        double recon    = t5 / (double)nrec;
        out[0] = (float)(coord + width + 2.0 * validity + 0.2 * cont + 0.1 * recon);

        // self-reset for the next graph replay
        g_ticket = 0u;
        g_work   = 0u;
#pragma unroll
        for (int q = 0; q < 6; q++) g_acc[q] = 0.f;
        __threadfence();
    }
}

extern "C" void kernel_launch(void* const* d_in, const int* in_sizes, int n_in,
                              void* d_out, int out_size)
{
    const float* preds = (const float*)d_in[0];
    const float* tgts  = (const float*)d_in[1];
    const float* rec   = (const float*)d_in[2];
    const float* img   = (const float*)d_in[3];

    const int B    = in_sizes[0] / (M_ROW * 9);
    const int nrec = in_sizes[2];

    loss_fused_kernel<<<NBLOCKS, TPB>>>(preds, tgts, rec, img,
                                        (float*)d_out, B, nrec);
}

// round 17
// speedup vs baseline: 3.1771x; 1.0039x over previous
#include <cuda_runtime.h>
#include <cstdint>

// ImprovedVectorizationLoss: fused masked-L1 + BCE + continuity + recon-MSE.
// R17: identical to R16 (persistent work-stealing cp.async pipeline, 888
// blocks = 6/SM, ballot+group-table continuity) with the recon-MSE stream
// manually unrolled x4 (batched loads) to raise its MLP from ~1 to ~8.

#define M_ROW 4096
#define TPB   256
#define SEGS  8
#define SEG   (M_ROW / SEGS)         // 512
#define TILE  256
#define NTILE (SEG / TILE)           // 2
#define NF4T  (TILE * 9 / 4)         // 576 float4 per tile per tensor
#define NBLOCKS 888                  // 6 blocks/SM x 148 SMs, single wave
#define BMAX  512
#define EPSV  1e-7f

__device__ float        g_acc[6];    // [coord,width,bce,nvalid,cont,recon]
__device__ unsigned int g_ticket;
__device__ unsigned int g_work;
__device__ int          g_first_idx[BMAX * SEGS];   // 0 if any valid, SEG if none
__device__ float2       g_first_p45[BMAX * SEGS];
__device__ float2       g_last_p45[BMAX * SEGS];

__device__ __forceinline__ float warpReduceSumF(float v) {
#pragma unroll
    for (int o = 16; o > 0; o >>= 1) v += __shfl_down_sync(0xffffffffu, v, o);
    return v;
}

__device__ __forceinline__ void cp16(void* s, const void* g) {
    unsigned saddr = (unsigned)__cvta_generic_to_shared(s);
    asm volatile("cp.async.cg.shared.global [%0], [%1], 16;" :: "r"(saddr), "l"(g));
}
#define CP_COMMIT() asm volatile("cp.async.commit_group;")
#define CP_WAIT(n)  asm volatile("cp.async.wait_group %0;" :: "n"(n))

__global__ __launch_bounds__(TPB, 6) void loss_fused_kernel(
    const float* __restrict__ preds, const float* __restrict__ tgts,
    const float* __restrict__ rec,   const float* __restrict__ img,
    float* __restrict__ out, int B, int nrec)
{
    __shared__ float         sp[NTILE * TILE * 9];   // 18 KB
    __shared__ float         st[NTILE * TILE * 9];   // 18 KB
    __shared__ float2        sgrp_first[16];         // per-group first-valid p45
    __shared__ unsigned char sflag[16];              // per-group any-valid flag
    __shared__ float         swred[6][8];
    __shared__ int           s_seg;
    __shared__ int           slast;

    const int tid  = threadIdx.x;
    const int bid  = blockIdx.x;
    const int lane = tid & 31;
    const int wid  = tid >> 5;
    const int NSEG = B * SEGS;

    float coordS = 0.f, widthS = 0.f, bceS = 0.f, nvS = 0.f, contS = 0.f, reconS = 0.f;

    // ---- prologue: steal first segment, prefetch both tiles ----
    if (tid == 0) s_seg = (int)atomicAdd(&g_work, 1u);
    __syncthreads();
    int seg = s_seg;

    if (seg < NSEG) {
        const float4* p4 = reinterpret_cast<const float4*>(preds + (size_t)seg * SEG * 9);
        const float4* t4 = reinterpret_cast<const float4*>(tgts  + (size_t)seg * SEG * 9);
#pragma unroll
        for (int tl = 0; tl < NTILE; tl++) {
            float4* spd = reinterpret_cast<float4*>(sp) + tl * NF4T;
            float4* std_ = reinterpret_cast<float4*>(st) + tl * NF4T;
            for (int i = tid; i < NF4T; i += TPB) {
                cp16(&spd[i], &p4[tl * NF4T + i]);
                cp16(&std_[i], &t4[tl * NF4T + i]);
            }
            CP_COMMIT();
        }
    }

    // ---- recon MSE burst, unrolled x4 with batched loads (MLP ~8) ----
    {
        const float4* r4 = reinterpret_cast<const float4*>(rec);
        const float4* i4 = reinterpret_cast<const float4*>(img);
        const int n4 = nrec >> 2;
        const int stride = NBLOCKS * TPB;
        int i = bid * TPB + tid;
        for (; i + 3 * stride < n4; i += 4 * stride) {
            float4 r0 = r4[i],              m0 = i4[i];
            float4 r1 = r4[i + stride],     m1 = i4[i + stride];
            float4 r2 = r4[i + 2 * stride], m2 = i4[i + 2 * stride];
            float4 r3 = r4[i + 3 * stride], m3 = i4[i + 3 * stride];
            float dx, dy, dz, dw;
            dx = r0.x - m0.x; dy = r0.y - m0.y; dz = r0.z - m0.z; dw = r0.w - m0.w;
            reconS += dx * dx + dy * dy + dz * dz + dw * dw;
            dx = r1.x - m1.x; dy = r1.y - m1.y; dz = r1.z - m1.z; dw = r1.w - m1.w;
            reconS += dx * dx + dy * dy + dz * dz + dw * dw;
            dx = r2.x - m2.x; dy = r2.y - m2.y; dz = r2.z - m2.z; dw = r2.w - m2.w;
            reconS += dx * dx + dy * dy + dz * dz + dw * dw;
            dx = r3.x - m3.x; dy = r3.y - m3.y; dz = r3.z - m3.z; dw = r3.w - m3.w;
            reconS += dx * dx + dy * dy + dz * dz + dw * dw;
        }
        for (; i < n4; i += stride) {
            float4 r = r4[i], m = i4[i];
            float dx = r.x - m.x, dy = r.y - m.y, dz = r.z - m.z, dw = r.w - m.w;
            reconS += dx * dx + dy * dy + dz * dz + dw * dw;
        }
    }

    // ---- persistent segment loop ----
    while (seg < NSEG) {
        if (tid == 0) s_seg = (int)atomicAdd(&g_work, 1u);   // steal next early

        unsigned pend0 = 0u, pend1 = 0u;   // "last valid in my group" markers
        float2   q45[2];
#pragma unroll
        for (int tile = 0; tile < NTILE; tile++) {
            if (tile == 0) CP_WAIT(1); else CP_WAIT(0);
            __syncthreads();   // tile data visible (also publishes s_seg)

            const float* pr = sp + (tile * TILE + tid) * 9;
            const float* tr = st + (tile * TILE + tid) * 9;
            float t8   = tr[8];
            bool  v    = (t8 > 0.5f);
            float mask = v ? 1.0f : 0.0f;

            float a4 = pr[4], a5 = pr[5];
            coordS += (fabsf(pr[0] - tr[0]) + fabsf(pr[1] - tr[1]) + fabsf(pr[2] - tr[2])
                     + fabsf(pr[3] - tr[3]) + fabsf(a4 - tr[4]) + fabsf(a5 - tr[5])) * mask;
            widthS += (fabsf(pr[6] - tr[6]) + fabsf(pr[7] - tr[7])) * mask;

            float p = fminf(fmaxf(pr[8], EPSV), 1.0f - EPSV);
            bceS   += -(t8 * __logf(p) + (1.0f - t8) * __logf(1.0f - p));
            nvS    += mask;

            q45[tile] = make_float2(a4, a5);

            // in-warp continuity: ballot + shfl (no smem array)
            unsigned b   = __ballot_sync(0xffffffffu, v);
            unsigned rem = (lane < 31) ? (b & (0xFFFFFFFEu << lane)) : 0u;
            int nx = rem ? (__ffs(rem) - 1) : 0;
            float nbx = __shfl_sync(0xffffffffu, a4, nx);
            float nby = __shfl_sync(0xffffffffu, a5, nx);
            if (v && rem) contS += 0.5f * (fabsf(a4 - nbx) + fabsf(a5 - nby));
            if (tile == 0) pend0 = (v && !rem) ? 1u : 0u;
            else           pend1 = (v && !rem) ? 1u : 0u;

            const int g = tile * 8 + wid;
            if (b != 0u && lane == (__ffs(b) - 1)) sgrp_first[g] = make_float2(a4, a5);
            if (lane == 0) sflag[g] = (b != 0u) ? 1 : 0;
        }
        __syncthreads();   // sp/st consumed; group tables visible

        const int segn = s_seg;

        // ---- prefetch next segment into the freed buffers ----
        if (segn < NSEG) {
            const float4* p4 = reinterpret_cast<const float4*>(preds + (size_t)segn * SEG * 9);
            const float4* t4 = reinterpret_cast<const float4*>(tgts  + (size_t)segn * SEG * 9);
#pragma unroll
            for (int tl = 0; tl < NTILE; tl++) {
                float4* spd = reinterpret_cast<float4*>(sp) + tl * NF4T;
                float4* std_ = reinterpret_cast<float4*>(st) + tl * NF4T;
                for (int i = tid; i < NF4T; i += TPB) {
                    cp16(&spd[i], &p4[tl * NF4T + i]);
                    cp16(&std_[i], &t4[tl * NF4T + i]);
                }
                CP_COMMIT();
            }
        }

        // ---- cross-group continuity resolution (under the prefetch) ----
        const int rs = seg;
#pragma unroll
        for (int t = 0; t < 2; t++) {
            unsigned pend = t ? pend1 : pend0;
            if (pend) {
                const int g = t * 8 + wid;
                bool found = false;
                float2 nb = make_float2(0.f, 0.f);
                for (int g2 = g + 1; g2 < 16 && !found; g2++) {
                    if (sflag[g2]) { nb = sgrp_first[g2]; found = true; }
                }
                if (found) {
                    contS += 0.5f * (fabsf(q45[t].x - nb.x) + fabsf(q45[t].y - nb.y));
                } else {
                    g_last_p45[rs] = q45[t];   // unique last valid in segment
                }
            }
        }
        if (tid == 0) {
            int fg = -1;
#pragma unroll
            for (int g2 = 15; g2 >= 0; g2--)
                if (sflag[g2]) fg = g2;
            g_first_idx[rs] = (fg >= 0) ? 0 : SEG;
            if (fg >= 0) g_first_p45[rs] = sgrp_first[fg];
        }

        seg = segn;
        // loop-top CP_WAIT+syncthreads orders these table reads before the
        // next segment's table writes.
    }

    // ---- block reduce + global atomic accumulate ----
    float vals[6] = {coordS, widthS, bceS, nvS, contS, reconS};
#pragma unroll
    for (int q = 0; q < 6; q++) {
        float v = warpReduceSumF(vals[q]);
        if (lane == 0) swred[q][wid] = v;
    }
    __syncthreads();
    if (wid == 0 && lane < 6) {
        float v = 0.f;
#pragma unroll
        for (int j = 0; j < 8; j++) v += swred[lane][j];
        atomicAdd(&g_acc[lane], v);
    }
    __syncthreads();

    // ---- last-block finalize ----
    if (tid == 0) {
        __threadfence();   // release: publishes this block's writes (cumulative)
        unsigned int t = atomicAdd(&g_ticket, 1u);
        slast = (t == (unsigned int)(NBLOCKS - 1)) ? 1 : 0;
    }
    __syncthreads();
    if (!slast) return;
    __threadfence();       // acquire (single block)

    // cross-segment continuity fixup: one row per thread, prefetched loads
    float fix = 0.f;
    for (int r = tid; r < B; r += TPB) {
        int    fidx[SEGS];
        float2 fp[SEGS], lp[SEGS];
#pragma unroll
        for (int s = 0; s < SEGS; s++) {
            int q = r * SEGS + s;
            fidx[s] = g_first_idx[q];
            fp[s]   = g_first_p45[q];
            lp[s]   = g_last_p45[q];
        }
        float2 nf = make_float2(0.f, 0.f);
        bool have = false;
#pragma unroll
        for (int s = SEGS - 1; s >= 0; s--) {
            if (fidx[s] < SEG) {
                if (have) fix += 0.5f * (fabsf(lp[s].x - nf.x) + fabsf(lp[s].y - nf.y));
                nf = fp[s];
                have = true;
            }
        }
    }
    {
        float v = warpReduceSumF(fix);
        if (lane == 0) swred[0][wid] = v;
    }
    __syncthreads();
    if (tid == 0) {
        float fsum = 0.f;
#pragma unroll
        for (int j = 0; j < 8; j++) fsum += swred[0][j];

        double t0 = (double)g_acc[0], t1 = (double)g_acc[1], t2 = (double)g_acc[2];
        double nv = (double)g_acc[3];
        double t4 = (double)g_acc[4] + (double)fsum;
        double t5 = (double)g_acc[5];

        double coord    = (nv > 0.0) ? t0 / fmax(nv * 6.0, 1.0) : 0.0;
        double width    = (nv > 0.0) ? t1 / fmax(nv * 2.0, 1.0) : 0.0;
        double validity = t2 / ((double)B * (double)M_ROW);
        double cont     = t4 / (double)B;
        double recon    = t5 / (double)nrec;
        out[0] = (float)(coord + width + 2.0 * validity + 0.2 * cont + 0.1 * recon);

        // self-reset for the next graph replay
        g_ticket = 0u;
        g_work   = 0u;
#pragma unroll
        for (int q = 0; q < 6; q++) g_acc[q] = 0.f;
        __threadfence();
    }
}

extern "C" void kernel_launch(void* const* d_in, const int* in_sizes, int n_in,
                              void* d_out, int out_size)
{
    const float* preds = (const float*)d_in[0];
    const float* tgts  = (const float*)d_in[1];
    const float* rec   = (const float*)d_in[2];
    const float* img   = (const float*)d_in[3];

    const int B    = in_sizes[0] / (M_ROW * 9);
    const int nrec = in_sizes[2];

    loss_fused_kernel<<<NBLOCKS, TPB>>>(preds, tgts, rec, img,
                                        (float*)d_out, B, nrec);
}